// round 7
// baseline (speedup 1.0000x reference)
#include <cuda_runtime.h>
#include <cuda_bf16.h>
#include <math.h>

#define B 32
#define L 256
#define D 512
#define MAX_LEN 2048                     // L * MAX_DUR(8)
#define ROWS_PB 32                       // output rows per block
#define BLOCKS_PER_BATCH (MAX_LEN / ROWS_PB)   // 64
#define F4_PER_ROW (D / 4)               // 128
#define ROWS_PT 16                       // rows per thread (t>>7 selects half)

// ---------------------------------------------------------------------------
// Fused length-regulator. Per block: recompute per-batch scan (cheap),
// derive source index for its 32 output rows, then copy: each thread owns
// one float4 column and 16 consecutive rows, issued as 16 INDEPENDENT
// LDG.128->STG.128 pairs (indices hoisted to registers, constant-stride
// addressing). Plain cached stores so L2 can absorb the write stream in
// the graph-replay steady state (output ~= L2 capacity).
// Grid = 2048 blocks x 256 threads.
// ---------------------------------------------------------------------------
__global__ void __launch_bounds__(256)
lr_fused_kernel(const float* __restrict__ att_out,
                const float* __restrict__ duration,
                const void*  __restrict__ alpha_ptr,
                float* __restrict__ out)
{
    const int b        = blockIdx.x / BLOCKS_PER_BATCH;
    const int row_base = (blockIdx.x % BLOCKS_PER_BATCH) * ROWS_PB;
    const int t    = threadIdx.x;       // 0..255
    const int lane = t & 31;
    const int wid  = t >> 5;            // 0..7

    // --- resolve alpha (int32 or float32, bit-sniffed) ---
    int   ab = *(const int*)alpha_ptr;
    float af = __int_as_float(ab);
    float alpha = (fabsf(af) >= 1e-30f && fabsf(af) <= 1e30f) ? af : (float)ab;

    // --- round (rintf = round-half-even, matches jnp.round) ---
    int r = (int)rintf(__ldg(&duration[b * L + t]) * alpha);

    // --- inclusive scan over 256 values ---
    int v = r;
    #pragma unroll
    for (int off = 1; off < 32; off <<= 1) {
        int n = __shfl_up_sync(0xffffffffu, v, off);
        if (lane >= off) v += n;
    }
    __shared__ int warp_tot[8];
    __shared__ int warp_pre[8];
    if (lane == 31) warp_tot[wid] = v;
    __syncthreads();
    if (t < 8) {
        int wv = warp_tot[t];
        #pragma unroll
        for (int off = 1; off < 8; off <<= 1) {
            int n = __shfl_up_sync(0xffu, wv, off);
            if (t >= off) wv += n;
        }
        warp_pre[t] = wv;
    }
    __syncthreads();
    int csum = v + (wid > 0 ? warp_pre[wid - 1] : 0);

    __shared__ int s_csum[L];
    s_csum[t] = csum;
    __syncthreads();

    const int total = s_csum[L - 1];

    // --- per-row source index for this block's 32 rows (-1 = masked) ---
    __shared__ int s_idx[ROWS_PB];
    if (t < ROWS_PB) {
        int pos = row_base + t;
        int outi;
        if (pos >= total) {
            outi = -1;
        } else {
            int lo = 0, hi = L;             // first i with csum[i] > pos
            while (lo < hi) {
                int mid = (lo + hi) >> 1;
                if (s_csum[mid] > pos) hi = mid; else lo = mid + 1;
            }
            outi = lo < (L - 1) ? lo : (L - 1);
        }
        s_idx[t] = outi;
    }
    __syncthreads();

    // --- expand copy: fixed column, 16 consecutive rows, no chaining ---
    const int rl  = t >> 7;                 // 0/1: which 16-row half
    const int col = t & 127;                // float4 column
    const int r0  = rl * ROWS_PT;

    // hoist indices into registers (LDS broadcast, warp-uniform rows)
    int idx[ROWS_PT];
    #pragma unroll
    for (int k = 0; k < ROWS_PT; k++)
        idx[k] = s_idx[r0 + k];

    const float4* __restrict__ src =
        (const float4*)(att_out + (size_t)b * L * D) + col;
    float4* __restrict__ dst =
        (float4*)(out + ((size_t)b * MAX_LEN + row_base + r0) * D) + col;
    const float4 zero = make_float4(0.f, 0.f, 0.f, 0.f);

    #pragma unroll
    for (int k = 0; k < ROWS_PT; k++) {
        float4 val = (idx[k] >= 0)
                   ? __ldg(src + (size_t)idx[k] * F4_PER_ROW)
                   : zero;
        dst[(size_t)k * F4_PER_ROW] = val;   // plain cached store
    }
}

extern "C" void kernel_launch(void* const* d_in, const int* in_sizes, int n_in,
                              void* d_out, int out_size)
{
    const float* att_out  = (const float*)d_in[0];
    const float* duration = (const float*)d_in[1];
    const void*  alpha    = d_in[2];

    lr_fused_kernel<<<B * BLOCKS_PER_BATCH, 256>>>(att_out, duration, alpha,
                                                   (float*)d_out);
}